// round 5
// baseline (speedup 1.0000x reference)
#include <cuda_runtime.h>
#include <math.h>

#define S_LEN 3072
#define D_MOD 512
#define NH 8
#define DH 64

// ---- scratch (no allocations allowed) ----
__device__ float g_Q[S_LEN * D_MOD];
__device__ float g_K[S_LEN * D_MOD];
__device__ float g_V[S_LEN * D_MOD];
__device__ float g_O[S_LEN * D_MOD];
__device__ float g_T[S_LEN * D_MOD];

struct QKVArgs {
    const float* W[3];
    const float* b[3];
    float* C[3];
};

// ---------------------------------------------------------------------------
// tf32 helpers (3xTF32 split: a = hi + lo, error ~2^-22 per element)
// ---------------------------------------------------------------------------
__device__ __forceinline__ unsigned f2tf(float f) {
    unsigned u;
    asm("cvt.rna.tf32.f32 %0, %1;" : "=r"(u) : "f"(f));
    return u;
}

__device__ __forceinline__ void tf32split(float f, unsigned& hi, unsigned& lo) {
    hi = f2tf(f);
    lo = f2tf(f - __uint_as_float(hi));
}

__device__ __forceinline__ void mma8(float* c,
    unsigned a0, unsigned a1, unsigned a2, unsigned a3,
    unsigned b0, unsigned b1)
{
    asm volatile(
        "mma.sync.aligned.m16n8k8.row.col.f32.tf32.tf32.f32 "
        "{%0,%1,%2,%3}, {%4,%5,%6,%7}, {%8,%9}, {%0,%1,%2,%3};"
        : "+f"(c[0]), "+f"(c[1]), "+f"(c[2]), "+f"(c[3])
        : "r"(a0), "r"(a1), "r"(a2), "r"(a3), "r"(b0), "r"(b1));
}

// 3x mma: c += al*bh + ah*bl + ah*bh
__device__ __forceinline__ void mma3x(float* c,
    const unsigned* ah, const unsigned* al,
    unsigned bh0, unsigned bh1, unsigned bl0, unsigned bl1)
{
    mma8(c, al[0], al[1], al[2], al[3], bh0, bh1);
    mma8(c, ah[0], ah[1], ah[2], ah[3], bl0, bl1);
    mma8(c, ah[0], ah[1], ah[2], ah[3], bh0, bh1);
}

// ---------------------------------------------------------------------------
// Block reductions (256 threads)
// ---------------------------------------------------------------------------
__device__ __forceinline__ float blockReduceMax256(float v, float* sh) {
    #pragma unroll
    for (int o = 16; o > 0; o >>= 1) v = fmaxf(v, __shfl_down_sync(0xffffffffu, v, o));
    int w = threadIdx.x >> 5;
    if ((threadIdx.x & 31) == 0) sh[w] = v;
    __syncthreads();
    if (threadIdx.x < 8) {
        float t = sh[threadIdx.x];
        #pragma unroll
        for (int o = 4; o > 0; o >>= 1) t = fmaxf(t, __shfl_down_sync(0xffu, t, o));
        if (threadIdx.x == 0) sh[0] = t;
    }
    __syncthreads();
    float r = sh[0];
    __syncthreads();
    return r;
}

__device__ __forceinline__ float blockReduceSum256(float v, float* sh) {
    #pragma unroll
    for (int o = 16; o > 0; o >>= 1) v += __shfl_down_sync(0xffffffffu, v, o);
    int w = threadIdx.x >> 5;
    if ((threadIdx.x & 31) == 0) sh[w] = v;
    __syncthreads();
    if (threadIdx.x < 8) {
        float t = sh[threadIdx.x];
        #pragma unroll
        for (int o = 4; o > 0; o >>= 1) t += __shfl_down_sync(0xffu, t, o);
        if (threadIdx.x == 0) sh[0] = t;
    }
    __syncthreads();
    float r = sh[0];
    __syncthreads();
    return r;
}

// reduce 3 sums at once; sh must have >= 24 floats
__device__ __forceinline__ float3 blockReduceSum3(float a, float b, float c, float* sh) {
    #pragma unroll
    for (int o = 16; o > 0; o >>= 1) {
        a += __shfl_down_sync(0xffffffffu, a, o);
        b += __shfl_down_sync(0xffffffffu, b, o);
        c += __shfl_down_sync(0xffffffffu, c, o);
    }
    int w = threadIdx.x >> 5;
    if ((threadIdx.x & 31) == 0) { sh[w] = a; sh[w + 8] = b; sh[w + 16] = c; }
    __syncthreads();
    if (threadIdx.x < 8) {
        a = sh[threadIdx.x]; b = sh[threadIdx.x + 8]; c = sh[threadIdx.x + 16];
        #pragma unroll
        for (int o = 4; o > 0; o >>= 1) {
            a += __shfl_down_sync(0xffu, a, o);
            b += __shfl_down_sync(0xffu, b, o);
            c += __shfl_down_sync(0xffu, c, o);
        }
        if (threadIdx.x == 0) { sh[0] = a; sh[8] = b; sh[16] = c; }
    }
    __syncthreads();
    float3 r = make_float3(sh[0], sh[8], sh[16]);
    __syncthreads();
    return r;
}

// ---------------------------------------------------------------------------
// Core 3xTF32 GEMM body with register-staged double buffering.
// CTA 64x64, BK=64, 8 warps (2m x 4n), warp tile 32x16. f32 smem tiles.
// A: [*, lda] row-major, tile rows = mbase..mbase+63, cols kt..kt+63
// B: [*, ldb] row-major, tile rows = kt..kt+63, cols nbase..nbase+63
// ---------------------------------------------------------------------------
__device__ __forceinline__ void gemm3x_body(
    const float* __restrict__ A, const float* __restrict__ B,
    float (*As)[68], float (*Bs)[72],
    int mbase, int nbase, int lda, int ldb, int kTotal,
    float c[2][2][4])
{
    int tid = threadIdx.x;
    int lane = tid & 31, wid = tid >> 5;
    int gid = lane >> 2, tig = lane & 3;
    int wm = wid & 1, wn = wid >> 1;
    int lr = tid >> 4;               // 0..63 (smem row this thread fills)
    int lc = (tid & 15) << 2;        // 0..60

    float4 ra[4], rb[4], ra2[4], rb2[4];
    #pragma unroll
    for (int i = 0; i < 4; i++) {
        int r = lr, cc = lc;          // rows lr, lr stays; use i*... need full 64 rows
        (void)r; (void)cc;
    }
    // initial load of tile kt=0 (each thread: 4 float4 of A, 4 of B)
    #pragma unroll
    for (int i = 0; i < 4; i++) {
        int idx = tid + i * 256;
        int r = idx >> 4;
        int cc = (idx & 15) << 2;
        ra[i] = *(const float4*)&A[(size_t)(mbase + r) * lda + cc];
        rb[i] = *(const float4*)&B[(size_t)r * ldb + nbase + cc];
    }

    for (int kt = 0; kt < kTotal; kt += 64) {
        #pragma unroll
        for (int i = 0; i < 4; i++) {
            int idx = tid + i * 256;
            int r = idx >> 4;
            int cc = (idx & 15) << 2;
            *(float4*)&As[r][cc] = ra[i];
            *(float4*)&Bs[r][cc] = rb[i];
        }
        __syncthreads();
        if (kt + 64 < kTotal) {
            #pragma unroll
            for (int i = 0; i < 4; i++) {
                int idx = tid + i * 256;
                int r = idx >> 4;
                int cc = (idx & 15) << 2;
                ra2[i] = *(const float4*)&A[(size_t)(mbase + r) * lda + kt + 64 + cc];
                rb2[i] = *(const float4*)&B[(size_t)(kt + 64 + r) * ldb + nbase + cc];
            }
        }
        #pragma unroll
        for (int ks = 0; ks < 8; ks++) {
            int kb = ks * 8;
            unsigned ah[2][4], al[2][4], bh[2][2], bl[2][2];
            #pragma unroll
            for (int mt = 0; mt < 2; mt++) {
                int rb0 = wm * 32 + mt * 16 + gid;
                tf32split(As[rb0][kb + tig],     ah[mt][0], al[mt][0]);
                tf32split(As[rb0 + 8][kb + tig], ah[mt][1], al[mt][1]);
                tf32split(As[rb0][kb + tig + 4],     ah[mt][2], al[mt][2]);
                tf32split(As[rb0 + 8][kb + tig + 4], ah[mt][3], al[mt][3]);
            }
            #pragma unroll
            for (int nt = 0; nt < 2; nt++) {
                int cb = wn * 16 + nt * 8 + gid;
                tf32split(Bs[kb + tig][cb],     bh[nt][0], bl[nt][0]);
                tf32split(Bs[kb + tig + 4][cb], bh[nt][1], bl[nt][1]);
            }
            #pragma unroll
            for (int mt = 0; mt < 2; mt++)
                #pragma unroll
                for (int nt = 0; nt < 2; nt++)
                    mma3x(c[mt][nt], ah[mt], al[mt], bh[nt][0], bh[nt][1], bl[nt][0], bl[nt][1]);
        }
        __syncthreads();
        #pragma unroll
        for (int i = 0; i < 4; i++) { ra[i] = ra2[i]; rb[i] = rb2[i]; }
    }
}

// ---------------------------------------------------------------------------
// Fused QKV projection: z-slice selects (W, b, C). A is x for all three.
// ---------------------------------------------------------------------------
__global__ __launch_bounds__(256) void qkv_tc(const float* __restrict__ A, QKVArgs args)
{
    __shared__ float As[64][68];
    __shared__ float Ws[64][72];
    int z = blockIdx.z;
    const float* W = args.W[z];
    const float* bias = args.b[z];
    float* C = args.C[z];
    int mbase = blockIdx.y * 64;
    int nbase = blockIdx.x * 64;

    float c[2][2][4] = {};
    gemm3x_body(A, W, As, Ws, mbase, nbase, D_MOD, D_MOD, D_MOD, c);

    int tid = threadIdx.x;
    int lane = tid & 31, wid = tid >> 5;
    int gid = lane >> 2, tig = lane & 3;
    int wm = wid & 1, wn = wid >> 1;
    #pragma unroll
    for (int mt = 0; mt < 2; mt++) {
        int r0 = mbase + wm * 32 + mt * 16 + gid;
        #pragma unroll
        for (int nt = 0; nt < 2; nt++) {
            int col = nbase + wn * 16 + nt * 8 + 2 * tig;
            float bx = bias[col], by = bias[col + 1];
            float2 o0; o0.x = c[mt][nt][0] + bx; o0.y = c[mt][nt][1] + by;
            *(float2*)&C[(size_t)r0 * D_MOD + col] = o0;
            float2 o1; o1.x = c[mt][nt][2] + bx; o1.y = c[mt][nt][3] + by;
            *(float2*)&C[(size_t)(r0 + 8) * D_MOD + col] = o1;
        }
    }
}

// ---------------------------------------------------------------------------
// Output projection: C = A @ W + bias
// ---------------------------------------------------------------------------
__global__ __launch_bounds__(256) void proj_tc(
    const float* __restrict__ A, const float* __restrict__ W,
    const float* __restrict__ bias, float* __restrict__ C)
{
    __shared__ float As[64][68];
    __shared__ float Ws[64][72];
    int mbase = blockIdx.y * 64;
    int nbase = blockIdx.x * 64;

    float c[2][2][4] = {};
    gemm3x_body(A, W, As, Ws, mbase, nbase, D_MOD, D_MOD, D_MOD, c);

    int tid = threadIdx.x;
    int lane = tid & 31, wid = tid >> 5;
    int gid = lane >> 2, tig = lane & 3;
    int wm = wid & 1, wn = wid >> 1;
    #pragma unroll
    for (int mt = 0; mt < 2; mt++) {
        int r0 = mbase + wm * 32 + mt * 16 + gid;
        #pragma unroll
        for (int nt = 0; nt < 2; nt++) {
            int col = nbase + wn * 16 + nt * 8 + 2 * tig;
            float bx = bias[col], by = bias[col + 1];
            float2 o0; o0.x = c[mt][nt][0] + bx; o0.y = c[mt][nt][1] + by;
            *(float2*)&C[(size_t)r0 * D_MOD + col] = o0;
            float2 o1; o1.x = c[mt][nt][2] + bx; o1.y = c[mt][nt][3] + by;
            *(float2*)&C[(size_t)(r0 + 8) * D_MOD + col] = o1;
        }
    }
}

// ---------------------------------------------------------------------------
// AV (3xTF32): O[q, h*64+d] = sum_k attn[h,q,k] * V[k, h*64+d]
// CTA 64(q) x 64(d), BK=64 over S, double-buffered.
// ---------------------------------------------------------------------------
__global__ __launch_bounds__(256) void av_tc(
    const float* __restrict__ attn, const float* __restrict__ V,
    float* __restrict__ O)
{
    __shared__ float As[64][68];
    __shared__ float Vs[64][72];
    int h = blockIdx.y;
    int mbase = blockIdx.x * 64;
    const float* ap = attn + (size_t)h * S_LEN * S_LEN;

    float c[2][2][4] = {};
    gemm3x_body(ap, V, As, Vs, mbase, h * DH, S_LEN, D_MOD, S_LEN, c);

    int tid = threadIdx.x;
    int lane = tid & 31, wid = tid >> 5;
    int gid = lane >> 2, tig = lane & 3;
    int wm = wid & 1, wn = wid >> 1;
    #pragma unroll
    for (int mt = 0; mt < 2; mt++) {
        int r0 = mbase + wm * 32 + mt * 16 + gid;
        #pragma unroll
        for (int nt = 0; nt < 2; nt++) {
            int col = h * DH + wn * 16 + nt * 8 + 2 * tig;
            float2 o0; o0.x = c[mt][nt][0]; o0.y = c[mt][nt][1];
            *(float2*)&O[(size_t)r0 * D_MOD + col] = o0;
            float2 o1; o1.x = c[mt][nt][2]; o1.y = c[mt][nt][3];
            *(float2*)&O[(size_t)(r0 + 8) * D_MOD + col] = o1;
        }
    }
}

// ---------------------------------------------------------------------------
// Logits (3xTF32): attn[h,q,k] = (1/8) * dot(Q[q, h*64:], K[k, h*64:])
// CTA 64(q) x 64(k), K-dim 64 resident (single tile, no pipeline needed).
// ---------------------------------------------------------------------------
__global__ __launch_bounds__(256) void qk_tc(
    const float* __restrict__ Q, const float* __restrict__ Km,
    float* __restrict__ attn)
{
    __shared__ float Qs[64][68];
    __shared__ float Ks[64][68];
    int h = blockIdx.z;
    int qbase = blockIdx.y * 64;
    int kbase = blockIdx.x * 64;
    int tid = threadIdx.x;
    int lane = tid & 31, wid = tid >> 5;
    int gid = lane >> 2, tig = lane & 3;
    int wm = wid & 1, wn = wid >> 1;

    #pragma unroll
    for (int i = 0; i < 4; i++) {
        int idx = tid + i * 256;
        int r = idx >> 4;
        int cc = (idx & 15) << 2;
        *(float4*)&Qs[r][cc] = *(const float4*)&Q[(size_t)(qbase + r) * D_MOD + h * DH + cc];
        *(float4*)&Ks[r][cc] = *(const float4*)&Km[(size_t)(kbase + r) * D_MOD + h * DH + cc];
    }
    __syncthreads();

    float c[2][2][4] = {};
    #pragma unroll
    for (int ks = 0; ks < 8; ks++) {
        int kb = ks * 8;
        unsigned ah[2][4], al[2][4], bh[2][2], bl[2][2];
        #pragma unroll
        for (int mt = 0; mt < 2; mt++) {
            int rb0 = wm * 32 + mt * 16 + gid;
            tf32split(Qs[rb0][kb + tig],     ah[mt][0], al[mt][0]);
            tf32split(Qs[rb0 + 8][kb + tig], ah[mt][1], al[mt][1]);
            tf32split(Qs[rb0][kb + tig + 4],     ah[mt][2], al[mt][2]);
            tf32split(Qs[rb0 + 8][kb + tig + 4], ah[mt][3], al[mt][3]);
        }
        #pragma unroll
        for (int nt = 0; nt < 2; nt++) {
            int cb = wn * 16 + nt * 8 + gid;
            tf32split(Ks[cb][kb + tig],     bh[nt][0], bl[nt][0]);
            tf32split(Ks[cb][kb + tig + 4], bh[nt][1], bl[nt][1]);
        }
        #pragma unroll
        for (int mt = 0; mt < 2; mt++)
            #pragma unroll
            for (int nt = 0; nt < 2; nt++)
                mma3x(c[mt][nt], ah[mt], al[mt], bh[nt][0], bh[nt][1], bl[nt][0], bl[nt][1]);
    }

    size_t base = (size_t)h * S_LEN * S_LEN;
    #pragma unroll
    for (int mt = 0; mt < 2; mt++) {
        int r0 = qbase + wm * 32 + mt * 16 + gid;
        #pragma unroll
        for (int nt = 0; nt < 2; nt++) {
            int col = kbase + wn * 16 + nt * 8 + 2 * tig;
            float2 o0; o0.x = c[mt][nt][0] * 0.125f; o0.y = c[mt][nt][1] * 0.125f;
            *(float2*)&attn[base + (size_t)r0 * S_LEN + col] = o0;
            float2 o1; o1.x = c[mt][nt][2] * 0.125f; o1.y = c[mt][nt][3] * 0.125f;
            *(float2*)&attn[base + (size_t)(r0 + 8) * S_LEN + col] = o1;
        }
    }
}

// ---------------------------------------------------------------------------
// 1.5-entmax, in place over rows of length 3072 (float4 I/O).
// X=(L-max)/2; 9 rounds of 3-point bisection (18 bits on tau),
// then exact quadratic solve on the identified support.
// ---------------------------------------------------------------------------
__global__ __launch_bounds__(256) void entmax_kernel(float* __restrict__ attn)
{
    __shared__ float sh[24];
    float4* p4 = (float4*)(attn + (size_t)blockIdx.x * S_LEN);
    int tid = threadIdx.x;

    float x[12];
    #pragma unroll
    for (int i = 0; i < 3; i++)
        *(float4*)&x[i * 4] = p4[tid + (i << 8)];

    float m = x[0];
    #pragma unroll
    for (int i = 1; i < 12; i++) m = fmaxf(m, x[i]);
    m = blockReduceMax256(m, sh);

    #pragma unroll
    for (int i = 0; i < 12; i++) x[i] = (x[i] - m) * 0.5f;

    // root of f(tau)=sum((x-tau)+^2)-1 lies in [-1, 0]
    float lo = -1.0f, hi = 0.0f;
    for (int it = 0; it < 9; it++) {
        float w = (hi - lo) * 0.25f;
        float m1 = lo + w, m2 = lo + 2.0f * w, m3 = hi - w;
        float s1 = 0.0f, s2 = 0.0f, s3 = 0.0f;
        #pragma unroll
        for (int i = 0; i < 12; i++) {
            float d1 = fmaxf(x[i] - m1, 0.0f); s1 += d1 * d1;
            float d2 = fmaxf(x[i] - m2, 0.0f); s2 += d2 * d2;
            float d3 = fmaxf(x[i] - m3, 0.0f); s3 += d3 * d3;
        }
        float3 r = blockReduceSum3(s1, s2, s3, sh);
        if (r.z > 1.0f)      { lo = m3; }
        else if (r.y > 1.0f) { lo = m2; hi = m3; }
        else if (r.x > 1.0f) { lo = m1; hi = m2; }
        else                 { hi = m1; }
    }
    float tau_b = 0.5f * (lo + hi);

    // exact solve on support {x > tau_b}
    float s1 = 0.0f, s2 = 0.0f, cn = 0.0f;
    #pragma unroll
    for (int i = 0; i < 12; i++) {
        if (x[i] > tau_b) { s1 += x[i]; s2 += x[i] * x[i]; cn += 1.0f; }
    }
    float3 r = blockReduceSum3(s1, s2, cn, sh);
    float n = fmaxf(r.z, 1.0f);
    float disc = fmaxf(r.x * r.x - n * (r.y - 1.0f), 0.0f);
    float tstar = (r.x - sqrtf(disc)) / n;

    float y[12];
    #pragma unroll
    for (int i = 0; i < 12; i++) {
        float d = fmaxf(x[i] - tstar, 0.0f);
        y[i] = d * d;
    }
    #pragma unroll
    for (int i = 0; i < 3; i++)
        p4[tid + (i << 8)] = *(float4*)&y[i * 4];
}

// ---------------------------------------------------------------------------
// LayerNorm(residual + proj): out = LN(t + x) * gamma + beta
// ---------------------------------------------------------------------------
__global__ __launch_bounds__(256) void ln_kernel(
    const float* __restrict__ t, const float* __restrict__ x,
    const float* __restrict__ gamma, const float* __restrict__ beta,
    float* __restrict__ out)
{
    __shared__ float sh[8];
    size_t base = (size_t)blockIdx.x * D_MOD;
    int tid = threadIdx.x;
    float v0 = t[base + tid]       + x[base + tid];
    float v1 = t[base + tid + 256] + x[base + tid + 256];
    float s = blockReduceSum256(v0 + v1, sh);
    float mu = s * (1.0f / 512.0f);
    float d0 = v0 - mu, d1 = v1 - mu;
    float vs = blockReduceSum256(d0 * d0 + d1 * d1, sh);
    float inv = rsqrtf(vs * (1.0f / 512.0f) + 1e-6f);
    out[base + tid]       = d0 * inv * gamma[tid]       + beta[tid];
    out[base + tid + 256] = d1 * inv * gamma[tid + 256] + beta[tid + 256];
}

// ---------------------------------------------------------------------------
extern "C" void kernel_launch(void* const* d_in, const int* in_sizes, int n_in,
                              void* d_out, int out_size)
{
    const float* x     = (const float*)d_in[0];
    const float* Wq    = (const float*)d_in[1];
    const float* bq    = (const float*)d_in[2];
    const float* Wk    = (const float*)d_in[3];
    const float* bk    = (const float*)d_in[4];
    const float* Wv    = (const float*)d_in[5];
    const float* bv    = (const float*)d_in[6];
    const float* Wo    = (const float*)d_in[7];
    const float* bo    = (const float*)d_in[8];
    const float* gamma = (const float*)d_in[9];
    const float* beta  = (const float*)d_in[10];

    float* out  = (float*)d_out;
    float* attn = out + (size_t)S_LEN * D_MOD;

    float *Qp, *Kp, *Vp, *Op, *Tp;
    cudaGetSymbolAddress((void**)&Qp, g_Q);
    cudaGetSymbolAddress((void**)&Kp, g_K);
    cudaGetSymbolAddress((void**)&Vp, g_V);
    cudaGetSymbolAddress((void**)&Op, g_O);
    cudaGetSymbolAddress((void**)&Tp, g_T);

    QKVArgs qa;
    qa.W[0] = Wq; qa.W[1] = Wk; qa.W[2] = Wv;
    qa.b[0] = bq; qa.b[1] = bk; qa.b[2] = bv;
    qa.C[0] = Qp; qa.C[1] = Kp; qa.C[2] = Vp;

    qkv_tc<<<dim3(D_MOD / 64, S_LEN / 64, 3), 256>>>(x, qa);

    qk_tc<<<dim3(S_LEN / 64, S_LEN / 64, NH), 256>>>(Qp, Kp, attn);

    entmax_kernel<<<NH * S_LEN, 256>>>(attn);

    av_tc<<<dim3(S_LEN / 64, NH), 256>>>(attn, Vp, Op);

    proj_tc<<<dim3(D_MOD / 64, S_LEN / 64), 256>>>(Op, Wo, bo, Tp);

    ln_kernel<<<S_LEN, 256>>>(Tp, x, gamma, beta, out);
}

// round 6
// speedup vs baseline: 1.0352x; 1.0352x over previous
#include <cuda_runtime.h>
#include <math.h>

#define S_LEN 3072
#define D_MOD 512
#define NH 8
#define DH 64

// ---- scratch (no allocations allowed) ----
__device__ float g_Q[S_LEN * D_MOD];
__device__ float g_K[S_LEN * D_MOD];
__device__ float g_V[S_LEN * D_MOD];
__device__ float g_O[S_LEN * D_MOD];
__device__ float g_T[S_LEN * D_MOD];

struct QKVArgs {
    const float* W[3];
    const float* b[3];
    float* C[3];
};

// dynamic smem layouts (in 32-bit words)
#define GEMM_SMEM_BYTES (4 * (2 * 64 * 68 + 2 * 64 * 72))   // 71680
#define QK_SMEM_BYTES   (4 * (4 * 64 * 68))                  // 69632

// ---------------------------------------------------------------------------
// tf32 helpers (3xTF32: a = hi + lo, missing term ~2^-22)
// ---------------------------------------------------------------------------
__device__ __forceinline__ unsigned f2tf(float f) {
    unsigned u;
    asm("cvt.rna.tf32.f32 %0, %1;" : "=r"(u) : "f"(f));
    return u;
}

__device__ __forceinline__ void tf32split(float f, unsigned& hi, unsigned& lo) {
    hi = f2tf(f);
    lo = f2tf(f - __uint_as_float(hi));
}

__device__ __forceinline__ void split4(float4 v, uint4& hi, uint4& lo) {
    tf32split(v.x, hi.x, lo.x);
    tf32split(v.y, hi.y, lo.y);
    tf32split(v.z, hi.z, lo.z);
    tf32split(v.w, hi.w, lo.w);
}

__device__ __forceinline__ void mma8(float* c,
    unsigned a0, unsigned a1, unsigned a2, unsigned a3,
    unsigned b0, unsigned b1)
{
    asm volatile(
        "mma.sync.aligned.m16n8k8.row.col.f32.tf32.tf32.f32 "
        "{%0,%1,%2,%3}, {%4,%5,%6,%7}, {%8,%9}, {%0,%1,%2,%3};"
        : "+f"(c[0]), "+f"(c[1]), "+f"(c[2]), "+f"(c[3])
        : "r"(a0), "r"(a1), "r"(a2), "r"(a3), "r"(b0), "r"(b1));
}

// 3x mma: c += al*bh + ah*bl + ah*bh
__device__ __forceinline__ void mma3x(float* c,
    const unsigned* ah, const unsigned* al,
    unsigned bh0, unsigned bh1, unsigned bl0, unsigned bl1)
{
    mma8(c, al[0], al[1], al[2], al[3], bh0, bh1);
    mma8(c, ah[0], ah[1], ah[2], ah[3], bl0, bl1);
    mma8(c, ah[0], ah[1], ah[2], ah[3], bh0, bh1);
}

// ---------------------------------------------------------------------------
// Block reductions (256 threads)
// ---------------------------------------------------------------------------
__device__ __forceinline__ float blockReduceMax256(float v, float* sh) {
    #pragma unroll
    for (int o = 16; o > 0; o >>= 1) v = fmaxf(v, __shfl_down_sync(0xffffffffu, v, o));
    int w = threadIdx.x >> 5;
    if ((threadIdx.x & 31) == 0) sh[w] = v;
    __syncthreads();
    if (threadIdx.x < 8) {
        float t = sh[threadIdx.x];
        #pragma unroll
        for (int o = 4; o > 0; o >>= 1) t = fmaxf(t, __shfl_down_sync(0xffu, t, o));
        if (threadIdx.x == 0) sh[0] = t;
    }
    __syncthreads();
    float r = sh[0];
    __syncthreads();
    return r;
}

__device__ __forceinline__ float blockReduceSum256(float v, float* sh) {
    #pragma unroll
    for (int o = 16; o > 0; o >>= 1) v += __shfl_down_sync(0xffffffffu, v, o);
    int w = threadIdx.x >> 5;
    if ((threadIdx.x & 31) == 0) sh[w] = v;
    __syncthreads();
    if (threadIdx.x < 8) {
        float t = sh[threadIdx.x];
        #pragma unroll
        for (int o = 4; o > 0; o >>= 1) t += __shfl_down_sync(0xffu, t, o);
        if (threadIdx.x == 0) sh[0] = t;
    }
    __syncthreads();
    float r = sh[0];
    __syncthreads();
    return r;
}

// reduce 3 sums at once; sh must have >= 24 floats
__device__ __forceinline__ float3 blockReduceSum3(float a, float b, float c, float* sh) {
    #pragma unroll
    for (int o = 16; o > 0; o >>= 1) {
        a += __shfl_down_sync(0xffffffffu, a, o);
        b += __shfl_down_sync(0xffffffffu, b, o);
        c += __shfl_down_sync(0xffffffffu, c, o);
    }
    int w = threadIdx.x >> 5;
    if ((threadIdx.x & 31) == 0) { sh[w] = a; sh[w + 8] = b; sh[w + 16] = c; }
    __syncthreads();
    if (threadIdx.x < 8) {
        a = sh[threadIdx.x]; b = sh[threadIdx.x + 8]; c = sh[threadIdx.x + 16];
        #pragma unroll
        for (int o = 4; o > 0; o >>= 1) {
            a += __shfl_down_sync(0xffu, a, o);
            b += __shfl_down_sync(0xffu, b, o);
            c += __shfl_down_sync(0xffu, c, o);
        }
        if (threadIdx.x == 0) { sh[0] = a; sh[8] = b; sh[16] = c; }
    }
    __syncthreads();
    float3 r = make_float3(sh[0], sh[8], sh[16]);
    __syncthreads();
    return r;
}

// ---------------------------------------------------------------------------
// Core 3xTF32 GEMM body, hi/lo split done ONCE at smem-store time.
// CTA 64x64, BK=64, 8 warps (2m x 4n), warp tile 32x16.
// A: [*, lda] row-major (rows mbase..+63, cols kt..kt+63)
// B: [*, ldb] row-major (rows kt..+63, cols nbase..+63)
// ---------------------------------------------------------------------------
__device__ __forceinline__ void gemm3x_body(
    const float* __restrict__ A, const float* __restrict__ B,
    int mbase, int nbase, int lda, int ldb, int kTotal,
    float c[2][2][4])
{
    extern __shared__ unsigned dsm[];
    unsigned (*Ah)[68] = (unsigned(*)[68])dsm;
    unsigned (*Al)[68] = (unsigned(*)[68])(dsm + 64 * 68);
    unsigned (*Bh)[72] = (unsigned(*)[72])(dsm + 2 * 64 * 68);
    unsigned (*Bl)[72] = (unsigned(*)[72])(dsm + 2 * 64 * 68 + 64 * 72);

    int tid = threadIdx.x;
    int lane = tid & 31, wid = tid >> 5;
    int gid = lane >> 2, tig = lane & 3;
    int wm = wid & 1, wn = wid >> 1;

    for (int kt = 0; kt < kTotal; kt += 64) {
        #pragma unroll
        for (int i = 0; i < 4; i++) {
            int idx = tid + i * 256;          // 0..1023
            int r = idx >> 4;                 // 0..63
            int cc = (idx & 15) << 2;         // 0..60
            float4 a4 = *(const float4*)&A[(size_t)(mbase + r) * lda + kt + cc];
            uint4 hi, lo; split4(a4, hi, lo);
            *(uint4*)&Ah[r][cc] = hi;
            *(uint4*)&Al[r][cc] = lo;
            float4 b4 = *(const float4*)&B[(size_t)(kt + r) * ldb + nbase + cc];
            split4(b4, hi, lo);
            *(uint4*)&Bh[r][cc] = hi;
            *(uint4*)&Bl[r][cc] = lo;
        }
        __syncthreads();
        #pragma unroll
        for (int ks = 0; ks < 8; ks++) {
            int kb = ks * 8;
            unsigned ah[2][4], al[2][4], bh[2][2], bl[2][2];
            #pragma unroll
            for (int mt = 0; mt < 2; mt++) {
                int rb0 = wm * 32 + mt * 16 + gid;
                ah[mt][0] = Ah[rb0][kb + tig];      al[mt][0] = Al[rb0][kb + tig];
                ah[mt][1] = Ah[rb0 + 8][kb + tig];  al[mt][1] = Al[rb0 + 8][kb + tig];
                ah[mt][2] = Ah[rb0][kb + tig + 4];      al[mt][2] = Al[rb0][kb + tig + 4];
                ah[mt][3] = Ah[rb0 + 8][kb + tig + 4];  al[mt][3] = Al[rb0 + 8][kb + tig + 4];
            }
            #pragma unroll
            for (int nt = 0; nt < 2; nt++) {
                int cb = wn * 16 + nt * 8 + gid;
                bh[nt][0] = Bh[kb + tig][cb];      bl[nt][0] = Bl[kb + tig][cb];
                bh[nt][1] = Bh[kb + tig + 4][cb];  bl[nt][1] = Bl[kb + tig + 4][cb];
            }
            #pragma unroll
            for (int mt = 0; mt < 2; mt++)
                #pragma unroll
                for (int nt = 0; nt < 2; nt++)
                    mma3x(c[mt][nt], ah[mt], al[mt], bh[nt][0], bh[nt][1], bl[nt][0], bl[nt][1]);
        }
        __syncthreads();
    }
}

// epilogue: write c + bias into C (ld = D_MOD)
__device__ __forceinline__ void epilogue_bias(
    float c[2][2][4], const float* __restrict__ bias, float* __restrict__ C,
    int mbase, int nbase)
{
    int tid = threadIdx.x;
    int lane = tid & 31, wid = tid >> 5;
    int gid = lane >> 2, tig = lane & 3;
    int wm = wid & 1, wn = wid >> 1;
    #pragma unroll
    for (int mt = 0; mt < 2; mt++) {
        int r0 = mbase + wm * 32 + mt * 16 + gid;
        #pragma unroll
        for (int nt = 0; nt < 2; nt++) {
            int col = nbase + wn * 16 + nt * 8 + 2 * tig;
            float bx = bias[col], by = bias[col + 1];
            float2 o0; o0.x = c[mt][nt][0] + bx; o0.y = c[mt][nt][1] + by;
            *(float2*)&C[(size_t)r0 * D_MOD + col] = o0;
            float2 o1; o1.x = c[mt][nt][2] + bx; o1.y = c[mt][nt][3] + by;
            *(float2*)&C[(size_t)(r0 + 8) * D_MOD + col] = o1;
        }
    }
}

// ---------------------------------------------------------------------------
// Fused QKV projection: z-slice selects (W, b, C). A is x for all three.
// ---------------------------------------------------------------------------
__global__ __launch_bounds__(256) void qkv_tc(const float* __restrict__ A, QKVArgs args)
{
    int z = blockIdx.z;
    int mbase = blockIdx.y * 64;
    int nbase = blockIdx.x * 64;
    float c[2][2][4] = {};
    gemm3x_body(A, args.W[z], mbase, nbase, D_MOD, D_MOD, D_MOD, c);
    epilogue_bias(c, args.b[z], args.C[z], mbase, nbase);
}

// ---------------------------------------------------------------------------
// Output projection: C = A @ W + bias
// ---------------------------------------------------------------------------
__global__ __launch_bounds__(256) void proj_tc(
    const float* __restrict__ A, const float* __restrict__ W,
    const float* __restrict__ bias, float* __restrict__ C)
{
    int mbase = blockIdx.y * 64;
    int nbase = blockIdx.x * 64;
    float c[2][2][4] = {};
    gemm3x_body(A, W, mbase, nbase, D_MOD, D_MOD, D_MOD, c);
    epilogue_bias(c, bias, C, mbase, nbase);
}

// ---------------------------------------------------------------------------
// AV (3xTF32): O[q, h*64+d] = sum_k attn[h,q,k] * V[k, h*64+d]
// ---------------------------------------------------------------------------
__global__ __launch_bounds__(256) void av_tc(
    const float* __restrict__ attn, const float* __restrict__ V,
    float* __restrict__ O)
{
    int h = blockIdx.y;
    int mbase = blockIdx.x * 64;
    const float* ap = attn + (size_t)h * S_LEN * S_LEN;
    float c[2][2][4] = {};
    gemm3x_body(ap, V, mbase, h * DH, S_LEN, D_MOD, S_LEN, c);

    int tid = threadIdx.x;
    int lane = tid & 31, wid = tid >> 5;
    int gid = lane >> 2, tig = lane & 3;
    int wm = wid & 1, wn = wid >> 1;
    #pragma unroll
    for (int mt = 0; mt < 2; mt++) {
        int r0 = mbase + wm * 32 + mt * 16 + gid;
        #pragma unroll
        for (int nt = 0; nt < 2; nt++) {
            int col = h * DH + wn * 16 + nt * 8 + 2 * tig;
            float2 o0; o0.x = c[mt][nt][0]; o0.y = c[mt][nt][1];
            *(float2*)&O[(size_t)r0 * D_MOD + col] = o0;
            float2 o1; o1.x = c[mt][nt][2]; o1.y = c[mt][nt][3];
            *(float2*)&O[(size_t)(r0 + 8) * D_MOD + col] = o1;
        }
    }
}

// ---------------------------------------------------------------------------
// Logits (3xTF32): attn[h,q,k] = (1/8)*dot(Q[q,h*64:],K[k,h*64:])
// Single K-tile of 64; hi/lo split at store.
// ---------------------------------------------------------------------------
__global__ __launch_bounds__(256) void qk_tc(
    const float* __restrict__ Q, const float* __restrict__ Km,
    float* __restrict__ attn)
{
    extern __shared__ unsigned dsm[];
    unsigned (*Qh)[68] = (unsigned(*)[68])dsm;
    unsigned (*Ql)[68] = (unsigned(*)[68])(dsm + 64 * 68);
    unsigned (*Kh)[68] = (unsigned(*)[68])(dsm + 2 * 64 * 68);
    unsigned (*Kl)[68] = (unsigned(*)[68])(dsm + 3 * 64 * 68);

    int h = blockIdx.z;
    int qbase = blockIdx.y * 64;
    int kbase = blockIdx.x * 64;
    int tid = threadIdx.x;
    int lane = tid & 31, wid = tid >> 5;
    int gid = lane >> 2, tig = lane & 3;
    int wm = wid & 1, wn = wid >> 1;

    #pragma unroll
    for (int i = 0; i < 4; i++) {
        int idx = tid + i * 256;
        int r = idx >> 4;
        int cc = (idx & 15) << 2;
        float4 q4 = *(const float4*)&Q[(size_t)(qbase + r) * D_MOD + h * DH + cc];
        uint4 hi, lo; split4(q4, hi, lo);
        *(uint4*)&Qh[r][cc] = hi;
        *(uint4*)&Ql[r][cc] = lo;
        float4 k4 = *(const float4*)&Km[(size_t)(kbase + r) * D_MOD + h * DH + cc];
        split4(k4, hi, lo);
        *(uint4*)&Kh[r][cc] = hi;
        *(uint4*)&Kl[r][cc] = lo;
    }
    __syncthreads();

    float c[2][2][4] = {};
    #pragma unroll
    for (int ks = 0; ks < 8; ks++) {
        int kb = ks * 8;
        unsigned ah[2][4], al[2][4], bh[2][2], bl[2][2];
        #pragma unroll
        for (int mt = 0; mt < 2; mt++) {
            int rb0 = wm * 32 + mt * 16 + gid;
            ah[mt][0] = Qh[rb0][kb + tig];      al[mt][0] = Ql[rb0][kb + tig];
            ah[mt][1] = Qh[rb0 + 8][kb + tig];  al[mt][1] = Ql[rb0 + 8][kb + tig];
            ah[mt][2] = Qh[rb0][kb + tig + 4];      al[mt][2] = Ql[rb0][kb + tig + 4];
            ah[mt][3] = Qh[rb0 + 8][kb + tig + 4];  al[mt][3] = Ql[rb0 + 8][kb + tig + 4];
        }
        #pragma unroll
        for (int nt = 0; nt < 2; nt++) {
            int cb = wn * 16 + nt * 8 + gid;
            bh[nt][0] = Kh[cb][kb + tig];      bl[nt][0] = Kl[cb][kb + tig];
            bh[nt][1] = Kh[cb][kb + tig + 4];  bl[nt][1] = Kl[cb][kb + tig + 4];
        }
        #pragma unroll
        for (int mt = 0; mt < 2; mt++)
            #pragma unroll
            for (int nt = 0; nt < 2; nt++)
                mma3x(c[mt][nt], ah[mt], al[mt], bh[nt][0], bh[nt][1], bl[nt][0], bl[nt][1]);
    }

    size_t base = (size_t)h * S_LEN * S_LEN;
    #pragma unroll
    for (int mt = 0; mt < 2; mt++) {
        int r0 = qbase + wm * 32 + mt * 16 + gid;
        #pragma unroll
        for (int nt = 0; nt < 2; nt++) {
            int col = kbase + wn * 16 + nt * 8 + 2 * tig;
            float2 o0; o0.x = c[mt][nt][0] * 0.125f; o0.y = c[mt][nt][1] * 0.125f;
            *(float2*)&attn[base + (size_t)r0 * S_LEN + col] = o0;
            float2 o1; o1.x = c[mt][nt][2] * 0.125f; o1.y = c[mt][nt][3] * 0.125f;
            *(float2*)&attn[base + (size_t)(r0 + 8) * S_LEN + col] = o1;
        }
    }
}

// ---------------------------------------------------------------------------
// 1.5-entmax, in place over rows of length 3072 (float4 I/O).
// ---------------------------------------------------------------------------
__global__ __launch_bounds__(256) void entmax_kernel(float* __restrict__ attn)
{
    __shared__ float sh[24];
    float4* p4 = (float4*)(attn + (size_t)blockIdx.x * S_LEN);
    int tid = threadIdx.x;

    float x[12];
    #pragma unroll
    for (int i = 0; i < 3; i++)
        *(float4*)&x[i * 4] = p4[tid + (i << 8)];

    float m = x[0];
    #pragma unroll
    for (int i = 1; i < 12; i++) m = fmaxf(m, x[i]);
    m = blockReduceMax256(m, sh);

    #pragma unroll
    for (int i = 0; i < 12; i++) x[i] = (x[i] - m) * 0.5f;

    // root of f(tau)=sum((x-tau)+^2)-1 lies in [-1, 0]
    float lo = -1.0f, hi = 0.0f;
    for (int it = 0; it < 9; it++) {
        float w = (hi - lo) * 0.25f;
        float m1 = lo + w, m2 = lo + 2.0f * w, m3 = hi - w;
        float s1 = 0.0f, s2 = 0.0f, s3 = 0.0f;
        #pragma unroll
        for (int i = 0; i < 12; i++) {
            float d1 = fmaxf(x[i] - m1, 0.0f); s1 += d1 * d1;
            float d2 = fmaxf(x[i] - m2, 0.0f); s2 += d2 * d2;
            float d3 = fmaxf(x[i] - m3, 0.0f); s3 += d3 * d3;
        }
        float3 r = blockReduceSum3(s1, s2, s3, sh);
        if (r.z > 1.0f)      { lo = m3; }
        else if (r.y > 1.0f) { lo = m2; hi = m3; }
        else if (r.x > 1.0f) { lo = m1; hi = m2; }
        else                 { hi = m1; }
    }
    float tau_b = 0.5f * (lo + hi);

    // exact solve on support {x > tau_b}
    float s1 = 0.0f, s2 = 0.0f, cn = 0.0f;
    #pragma unroll
    for (int i = 0; i < 12; i++) {
        if (x[i] > tau_b) { s1 += x[i]; s2 += x[i] * x[i]; cn += 1.0f; }
    }
    float3 r = blockReduceSum3(s1, s2, cn, sh);
    float n = fmaxf(r.z, 1.0f);
    float disc = fmaxf(r.x * r.x - n * (r.y - 1.0f), 0.0f);
    float tstar = (r.x - sqrtf(disc)) / n;

    float y[12];
    #pragma unroll
    for (int i = 0; i < 12; i++) {
        float d = fmaxf(x[i] - tstar, 0.0f);
        y[i] = d * d;
    }
    #pragma unroll
    for (int i = 0; i < 3; i++)
        p4[tid + (i << 8)] = *(float4*)&y[i * 4];
}

// ---------------------------------------------------------------------------
// LayerNorm(residual + proj): out = LN(t + x) * gamma + beta
// ---------------------------------------------------------------------------
__global__ __launch_bounds__(256) void ln_kernel(
    const float* __restrict__ t, const float* __restrict__ x,
    const float* __restrict__ gamma, const float* __restrict__ beta,
    float* __restrict__ out)
{
    __shared__ float sh[8];
    size_t base = (size_t)blockIdx.x * D_MOD;
    int tid = threadIdx.x;
    float v0 = t[base + tid]       + x[base + tid];
    float v1 = t[base + tid + 256] + x[base + tid + 256];
    float s = blockReduceSum256(v0 + v1, sh);
    float mu = s * (1.0f / 512.0f);
    float d0 = v0 - mu, d1 = v1 - mu;
    float vs = blockReduceSum256(d0 * d0 + d1 * d1, sh);
    float inv = rsqrtf(vs * (1.0f / 512.0f) + 1e-6f);
    out[base + tid]       = d0 * inv * gamma[tid]       + beta[tid];
    out[base + tid + 256] = d1 * inv * gamma[tid + 256] + beta[tid + 256];
}

// ---------------------------------------------------------------------------
extern "C" void kernel_launch(void* const* d_in, const int* in_sizes, int n_in,
                              void* d_out, int out_size)
{
    const float* x     = (const float*)d_in[0];
    const float* Wq    = (const float*)d_in[1];
    const float* bq    = (const float*)d_in[2];
    const float* Wk    = (const float*)d_in[3];
    const float* bk    = (const float*)d_in[4];
    const float* Wv    = (const float*)d_in[5];
    const float* bv    = (const float*)d_in[6];
    const float* Wo    = (const float*)d_in[7];
    const float* bo    = (const float*)d_in[8];
    const float* gamma = (const float*)d_in[9];
    const float* beta  = (const float*)d_in[10];

    float* out  = (float*)d_out;
    float* attn = out + (size_t)S_LEN * D_MOD;

    float *Qp, *Kp, *Vp, *Op, *Tp;
    cudaGetSymbolAddress((void**)&Qp, g_Q);
    cudaGetSymbolAddress((void**)&Kp, g_K);
    cudaGetSymbolAddress((void**)&Vp, g_V);
    cudaGetSymbolAddress((void**)&Op, g_O);
    cudaGetSymbolAddress((void**)&Tp, g_T);

    cudaFuncSetAttribute(qkv_tc,  cudaFuncAttributeMaxDynamicSharedMemorySize, GEMM_SMEM_BYTES);
    cudaFuncSetAttribute(proj_tc, cudaFuncAttributeMaxDynamicSharedMemorySize, GEMM_SMEM_BYTES);
    cudaFuncSetAttribute(av_tc,   cudaFuncAttributeMaxDynamicSharedMemorySize, GEMM_SMEM_BYTES);
    cudaFuncSetAttribute(qk_tc,   cudaFuncAttributeMaxDynamicSharedMemorySize, QK_SMEM_BYTES);

    QKVArgs qa;
    qa.W[0] = Wq; qa.W[1] = Wk; qa.W[2] = Wv;
    qa.b[0] = bq; qa.b[1] = bk; qa.b[2] = bv;
    qa.C[0] = Qp; qa.C[1] = Kp; qa.C[2] = Vp;

    qkv_tc<<<dim3(D_MOD / 64, S_LEN / 64, 3), 256, GEMM_SMEM_BYTES>>>(x, qa);

    qk_tc<<<dim3(S_LEN / 64, S_LEN / 64, NH), 256, QK_SMEM_BYTES>>>(Qp, Kp, attn);

    entmax_kernel<<<NH * S_LEN, 256>>>(attn);

    av_tc<<<dim3(S_LEN / 64, NH), 256, GEMM_SMEM_BYTES>>>(attn, Vp, Op);

    proj_tc<<<dim3(D_MOD / 64, S_LEN / 64), 256, GEMM_SMEM_BYTES>>>(Op, Wo, bo, Tp);

    ln_kernel<<<S_LEN, 256>>>(Tp, x, gamma, beta, out);
}